// round 1
// baseline (speedup 1.0000x reference)
#include <cuda_runtime.h>
#include <cuda_fp8.h>
#include <math.h>

#define B_ 2
#define N_ 2048
#define C_ 1024
#define H_ 16
#define D_ 64

// Scratch (allocation-free contract: __device__ globals)
__device__ float g_qkv[B_ * N_ * 3 * C_];    // [B,N,3,H,D] row-major as [B*N, 3C]
__device__ float g_att[B_ * N_ * C_];        // attention output [B,N,C] (head-major cols)
__device__ float g_scale[64];                // 448/amax  per (b,h,{q,k})
__device__ float g_iscale[64];               // amax/448

// ---------------------------------------------------------------------------
// Tiled SGEMM: C[M,N] = A[M,K] @ B[K,N] (+bias). BM=BN=64, BK=16, 256 thr, 4x4.
// ---------------------------------------------------------------------------
template <bool BIAS>
__global__ void sgemm64(const float* __restrict__ A, const float* __restrict__ Bm,
                        const float* __restrict__ bias, float* __restrict__ Cm,
                        int M, int N, int K) {
    __shared__ float As[16][68];   // [k][m], padded
    __shared__ float Bs[16][68];   // [k][n], padded
    const int bm = blockIdx.y * 64;
    const int bn = blockIdx.x * 64;
    const int tid = threadIdx.x;
    const int tx = tid & 15, ty = tid >> 4;

    float acc[4][4] = {};
    for (int t = 0; t < K; t += 16) {
        {   // A tile: 64 rows x 16 cols, one float4 per thread, store transposed
            int row = tid >> 2, col = (tid & 3) * 4;
            float4 a = *(const float4*)&A[(size_t)(bm + row) * K + t + col];
            As[col + 0][row] = a.x; As[col + 1][row] = a.y;
            As[col + 2][row] = a.z; As[col + 3][row] = a.w;
        }
        {   // B tile: 16 rows x 64 cols, one float4 per thread
            int row = tid >> 4, col = (tid & 15) * 4;
            *(float4*)&Bs[row][col] = *(const float4*)&Bm[(size_t)(t + row) * N + bn + col];
        }
        __syncthreads();
#pragma unroll
        for (int kk = 0; kk < 16; kk++) {
            float4 av = *(float4*)&As[kk][ty * 4];
            float4 bv = *(float4*)&Bs[kk][tx * 4];
            float a[4] = {av.x, av.y, av.z, av.w};
            float b[4] = {bv.x, bv.y, bv.z, bv.w};
#pragma unroll
            for (int i = 0; i < 4; i++)
#pragma unroll
                for (int j = 0; j < 4; j++) acc[i][j] += a[i] * b[j];
        }
        __syncthreads();
    }
#pragma unroll
    for (int i = 0; i < 4; i++) {
        float4 v;
        v.x = acc[i][0]; v.y = acc[i][1]; v.z = acc[i][2]; v.w = acc[i][3];
        if (BIAS) {
            const float* bb = &bias[bn + tx * 4];
            v.x += bb[0]; v.y += bb[1]; v.z += bb[2]; v.w += bb[3];
        }
        *(float4*)&Cm[(size_t)(bm + ty * 4 + i) * N + bn + tx * 4] = v;
    }
}

// ---------------------------------------------------------------------------
// Per-(b,h,{q,k}) amax over the [N,D] slab -> scale / inv-scale
// ---------------------------------------------------------------------------
__global__ void amax_kernel() {
    const int bw = blockIdx.x;           // ((b*16 + h)*2 + w), w: 0=q, 1=k
    const int w = bw & 1;
    const int h = (bw >> 1) & 15;
    const int b = bw >> 5;
    __shared__ float red[256];
    float mx = 0.f;
    for (int i = threadIdx.x; i < N_ * D_; i += 256) {
        int n = i >> 6, d = i & 63;
        float v = g_qkv[((size_t)(b * N_ + n)) * (3 * C_) + w * C_ + h * D_ + d];
        mx = fmaxf(mx, fabsf(v));
    }
    red[threadIdx.x] = mx;
    __syncthreads();
    for (int s = 128; s; s >>= 1) {
        if (threadIdx.x < s) red[threadIdx.x] = fmaxf(red[threadIdx.x], red[threadIdx.x + s]);
        __syncthreads();
    }
    if (threadIdx.x == 0) {
        float amax = fmaxf(red[0], 1e-12f);
        g_scale[bw]  = 448.f / amax;
        g_iscale[bw] = amax / 448.f;
    }
}

// ---------------------------------------------------------------------------
// fp8 e4m3 quantize-dequantize of Q and K in place (vectorized by float4)
// ---------------------------------------------------------------------------
__global__ void quant_kernel() {
    int gid = blockIdx.x * blockDim.x + threadIdx.x;   // 2*2048*2*256 = 2,097,152 float4s
    if (gid >= B_ * N_ * 2 * (C_ / 4)) return;
    int c4 = (gid & 255) * 4;           // column within the 1024-wide q or k chunk
    int w  = (gid >> 8) & 1;
    int n  = (gid >> 9) & 2047;
    int b  = gid >> 20;
    int h  = c4 >> 6;
    int si = (b * 16 + h) * 2 + w;
    float s  = g_scale[si];
    float is = g_iscale[si];
    size_t base = ((size_t)(b * N_ + n)) * (3 * C_) + w * C_ + c4;
    float4 v = *(float4*)&g_qkv[base];
    v.x = (float)__nv_fp8_e4m3(v.x * s) * is;
    v.y = (float)__nv_fp8_e4m3(v.y * s) * is;
    v.z = (float)__nv_fp8_e4m3(v.z * s) * is;
    v.w = (float)__nv_fp8_e4m3(v.w * s) * is;
    *(float4*)&g_qkv[base] = v;
}

// ---------------------------------------------------------------------------
// Causal flash attention fp32. Br=64 q-rows per block, Bc=32 k-cols per tile.
// 256 threads: thread (r = tid>>2, c = tid&3) owns 8 score cols, 16 O dims.
// ---------------------------------------------------------------------------
__global__ void flash_kernel() {
    const int qt = blockIdx.x, h = blockIdx.y, b = blockIdx.z;
    const int q0 = qt * 64;
    __shared__ float Qs[64][68];
    __shared__ float Ks[32][68];
    __shared__ float Vs[32][68];
    __shared__ float Ps[64][36];
    const int tid = threadIdx.x;

    // Load Q tile (64 x 64)
#pragma unroll
    for (int ll = 0; ll < 4; ll++) {
        int idx = tid + ll * 256;                 // 0..1023 float4s
        int r = idx >> 4, c4 = (idx & 15) * 4;
        *(float4*)&Qs[r][c4] =
            *(const float4*)&g_qkv[((size_t)(b * N_ + q0 + r)) * (3 * C_) + h * D_ + c4];
    }
    __syncthreads();

    const int r = tid >> 2, c = tid & 3;
    const int gq = q0 + r;
    float m = -INFINITY, l = 0.f;
    float o[16];
#pragma unroll
    for (int i = 0; i < 16; i++) o[i] = 0.f;

    for (int kt = 0; kt <= 2 * qt + 1; kt++) {
        const int k0 = kt * 32;
        // Load K,V tiles (32 x 64 each)
#pragma unroll
        for (int ll = 0; ll < 2; ll++) {
            int idx = tid + ll * 256;             // 0..511 float4s
            int rr = idx >> 4, c4 = (idx & 15) * 4;
            size_t g = ((size_t)(b * N_ + k0 + rr)) * (3 * C_) + C_ + h * D_ + c4;
            *(float4*)&Ks[rr][c4] = *(const float4*)&g_qkv[g];
            *(float4*)&Vs[rr][c4] = *(const float4*)&g_qkv[g + C_];
        }
        __syncthreads();

        // Scores: 8 cols per thread
        float s[8];
#pragma unroll
        for (int j = 0; j < 8; j++) s[j] = 0.f;
#pragma unroll
        for (int d0 = 0; d0 < 64; d0 += 4) {
            float4 qv = *(float4*)&Qs[r][d0];
#pragma unroll
            for (int j = 0; j < 8; j++) {
                float4 kv = *(float4*)&Ks[c * 8 + j][d0];
                s[j] += qv.x * kv.x + qv.y * kv.y + qv.z * kv.z + qv.w * kv.w;
            }
        }
        const float sm = 0.125f;                  // D^-0.5
#pragma unroll
        for (int j = 0; j < 8; j++) {
            int gk = k0 + c * 8 + j;
            s[j] = (gk <= gq) ? s[j] * sm : -1e30f;
        }
        // Row max across this thread's 8 + the 3 sibling threads (same warp)
        float mloc = s[0];
#pragma unroll
        for (int j = 1; j < 8; j++) mloc = fmaxf(mloc, s[j]);
        mloc = fmaxf(mloc, __shfl_xor_sync(0xffffffffu, mloc, 1));
        mloc = fmaxf(mloc, __shfl_xor_sync(0xffffffffu, mloc, 2));
        float mnew = fmaxf(m, mloc);
        float fac = __expf(m - mnew);
        float psum = 0.f;
#pragma unroll
        for (int j = 0; j < 8; j++) { s[j] = __expf(s[j] - mnew); psum += s[j]; }
        psum += __shfl_xor_sync(0xffffffffu, psum, 1);
        psum += __shfl_xor_sync(0xffffffffu, psum, 2);
        l = l * fac + psum;
        m = mnew;
#pragma unroll
        for (int dd = 0; dd < 16; dd++) o[dd] *= fac;
#pragma unroll
        for (int j = 0; j < 8; j++) Ps[r][c * 8 + j] = s[j];
        __syncwarp();
        // O += P @ V  (thread owns d-slice c*16..c*16+15)
#pragma unroll
        for (int j = 0; j < 32; j++) {
            float p = Ps[r][j];
            const float* vrow = &Vs[j][c * 16];
#pragma unroll
            for (int dd = 0; dd < 16; dd += 4) {
                float4 vv = *(const float4*)&vrow[dd];
                o[dd + 0] += p * vv.x; o[dd + 1] += p * vv.y;
                o[dd + 2] += p * vv.z; o[dd + 3] += p * vv.w;
            }
        }
        __syncthreads();
    }
    float inv = 1.f / l;
    size_t ob = ((size_t)(b * N_ + gq)) * C_ + h * D_ + c * 16;
#pragma unroll
    for (int dd = 0; dd < 16; dd += 4) {
        float4 v;
        v.x = o[dd] * inv; v.y = o[dd + 1] * inv; v.z = o[dd + 2] * inv; v.w = o[dd + 3] * inv;
        *(float4*)&g_att[ob + dd] = v;
    }
}

// ---------------------------------------------------------------------------
extern "C" void kernel_launch(void* const* d_in, const int* in_sizes, int n_in,
                              void* d_out, int out_size) {
    const float* x      = (const float*)d_in[0];   // [2,2048,1024]
    const float* w_qkv  = (const float*)d_in[1];   // [1024,3072]
    const float* w_proj = (const float*)d_in[2];   // [1024,1024]
    const float* b_proj = (const float*)d_in[3];   // [1024]
    float* out = (float*)d_out;                    // [2,2048,1024]

    float* qkv_ptr; cudaGetSymbolAddress((void**)&qkv_ptr, g_qkv);
    float* att_ptr; cudaGetSymbolAddress((void**)&att_ptr, g_att);

    // 1) QKV GEMM: [4096,1024] @ [1024,3072]
    {
        dim3 grid(3 * C_ / 64, (B_ * N_) / 64);
        sgemm64<false><<<grid, 256>>>(x, w_qkv, nullptr, qkv_ptr, B_ * N_, 3 * C_, C_);
    }
    // 2) amax -> scales
    amax_kernel<<<64, 256>>>();
    // 3) fp8 quant-dequant of Q,K in place
    quant_kernel<<<(B_ * N_ * 2 * (C_ / 4) + 255) / 256, 256>>>();
    // 4) causal flash attention
    {
        dim3 grid(N_ / 64, H_, B_);
        flash_kernel<<<grid, 256>>>();
    }
    // 5) output projection + bias
    {
        dim3 grid(C_ / 64, (B_ * N_) / 64);
        sgemm64<true><<<grid, 256>>>(att_ptr, w_proj, b_proj, out, B_ * N_, C_, C_);
    }
}

// round 2
// speedup vs baseline: 1.0280x; 1.0280x over previous
#include <cuda_runtime.h>
#include <cuda_fp8.h>
#include <math.h>

#define B_ 2
#define N_ 2048
#define C_ 1024
#define H_ 16
#define D_ 64

// Scratch (allocation-free contract: __device__ globals)
__device__ float g_qkv[B_ * N_ * 3 * C_];    // [B,N,3,H,D] row-major as [B*N, 3C]
__device__ float g_att[B_ * N_ * C_];        // attention output [B,N,C]
__device__ float g_scale[64];                // 448/amax  per (b,h,{q,k})
__device__ float g_iscale[64];               // amax/448

// ---------------------------------------------------------------------------
// TF32 helpers
// ---------------------------------------------------------------------------
__device__ __forceinline__ unsigned f2tf(float x) {
    unsigned u;
    asm("cvt.rna.tf32.f32 %0, %1;" : "=r"(u) : "f"(x));
    return u;
}

__device__ __forceinline__ void mma_tf32(float* d, const unsigned* a, const unsigned* b) {
    asm volatile(
        "mma.sync.aligned.m16n8k8.row.col.f32.tf32.tf32.f32 "
        "{%0,%1,%2,%3},{%4,%5,%6,%7},{%8,%9},{%0,%1,%2,%3};"
        : "+f"(d[0]), "+f"(d[1]), "+f"(d[2]), "+f"(d[3])
        : "r"(a[0]), "r"(a[1]), "r"(a[2]), "r"(a[3]), "r"(b[0]), "r"(b[1]));
}

// ---------------------------------------------------------------------------
// 3xTF32 GEMM: C[M,N] = A[M,K] @ B[K,N] (+bias), near-fp32 accuracy.
// Block 128x128, 8 warps (warp tile 32x64), K-step 16.
// smem strides chosen for conflict-free fragment loads:
//   As stride 20  -> bank(20m+k), m in 0..7 quad rows: perfect permutation
//   Bs stride 136 -> bank(8k+n) over the warp: perfect permutation
// ---------------------------------------------------------------------------
template <bool BIAS>
__global__ void gemm_tf32x3(const float* __restrict__ A, const float* __restrict__ Bm,
                            const float* __restrict__ bias, float* __restrict__ Cm,
                            int M, int N, int K) {
    __shared__ float As[128 * 20];
    __shared__ float Bs[16 * 136];
    const int bm = blockIdx.y * 128;
    const int bn = blockIdx.x * 128;
    const int tid = threadIdx.x;
    const int wid = tid >> 5, lane = tid & 31;
    const int gid = lane >> 2, tig = lane & 3;
    const int wm = (wid & 3) * 32;     // warp M offset within block
    const int wn = (wid >> 2) * 64;    // warp N offset within block

    float acc[2][8][4];
#pragma unroll
    for (int i = 0; i < 2; i++)
#pragma unroll
        for (int j = 0; j < 8; j++)
#pragma unroll
            for (int t = 0; t < 4; t++) acc[i][j][t] = 0.f;

    for (int kt = 0; kt < K; kt += 16) {
        __syncthreads();
        // A tile: 128 rows x 16 cols (2 float4 per thread)
#pragma unroll
        for (int l = 0; l < 2; l++) {
            int idx = tid + l * 256;           // 0..511
            int r = idx >> 2, c4 = (idx & 3) * 4;
            float4 v = *(const float4*)&A[(size_t)(bm + r) * K + kt + c4];
            float* p = &As[r * 20 + c4];
            p[0] = v.x; p[1] = v.y; p[2] = v.z; p[3] = v.w;
        }
        // B tile: 16 rows x 128 cols (2 float4 per thread)
#pragma unroll
        for (int l = 0; l < 2; l++) {
            int idx = tid + l * 256;           // 0..511
            int r = idx >> 5, c4 = (idx & 31) * 4;
            float4 v = *(const float4*)&Bm[(size_t)(kt + r) * N + bn + c4];
            float* p = &Bs[r * 136 + c4];
            p[0] = v.x; p[1] = v.y; p[2] = v.z; p[3] = v.w;
        }
        __syncthreads();

#pragma unroll
        for (int k8 = 0; k8 < 16; k8 += 8) {
            unsigned Ah[2][4], Al[2][4], Bh[8][2], Bl[8][2];
#pragma unroll
            for (int mt = 0; mt < 2; mt++) {
                int r0 = wm + mt * 16 + gid;
                float x0 = As[r0 * 20 + k8 + tig];
                float x1 = As[(r0 + 8) * 20 + k8 + tig];
                float x2 = As[r0 * 20 + k8 + tig + 4];
                float x3 = As[(r0 + 8) * 20 + k8 + tig + 4];
                Ah[mt][0] = f2tf(x0); Al[mt][0] = f2tf(x0 - __uint_as_float(Ah[mt][0]));
                Ah[mt][1] = f2tf(x1); Al[mt][1] = f2tf(x1 - __uint_as_float(Ah[mt][1]));
                Ah[mt][2] = f2tf(x2); Al[mt][2] = f2tf(x2 - __uint_as_float(Ah[mt][2]));
                Ah[mt][3] = f2tf(x3); Al[mt][3] = f2tf(x3 - __uint_as_float(Ah[mt][3]));
            }
#pragma unroll
            for (int nt = 0; nt < 8; nt++) {
                int c0 = wn + nt * 8 + gid;
                float y0 = Bs[(k8 + tig) * 136 + c0];
                float y1 = Bs[(k8 + tig + 4) * 136 + c0];
                Bh[nt][0] = f2tf(y0); Bl[nt][0] = f2tf(y0 - __uint_as_float(Bh[nt][0]));
                Bh[nt][1] = f2tf(y1); Bl[nt][1] = f2tf(y1 - __uint_as_float(Bh[nt][1]));
            }
#pragma unroll
            for (int mt = 0; mt < 2; mt++)
#pragma unroll
                for (int nt = 0; nt < 8; nt++) {
                    mma_tf32(acc[mt][nt], Al[mt], Bh[nt]);
                    mma_tf32(acc[mt][nt], Ah[mt], Bl[nt]);
                    mma_tf32(acc[mt][nt], Ah[mt], Bh[nt]);
                }
        }
    }

#pragma unroll
    for (int mt = 0; mt < 2; mt++)
#pragma unroll
        for (int nt = 0; nt < 8; nt++) {
            int r = bm + wm + mt * 16 + gid;
            int c = bn + wn + nt * 8 + 2 * tig;
            float b0 = 0.f, b1 = 0.f;
            if (BIAS) { b0 = bias[c]; b1 = bias[c + 1]; }
            Cm[(size_t)r * N + c]           = acc[mt][nt][0] + b0;
            Cm[(size_t)r * N + c + 1]       = acc[mt][nt][1] + b1;
            Cm[(size_t)(r + 8) * N + c]     = acc[mt][nt][2] + b0;
            Cm[(size_t)(r + 8) * N + c + 1] = acc[mt][nt][3] + b1;
        }
}

// ---------------------------------------------------------------------------
// Per-(b,h,{q,k}) amax over the [N,D] slab -> scale / inv-scale
// ---------------------------------------------------------------------------
__global__ void amax_kernel() {
    const int bw = blockIdx.x;           // ((b*16 + h)*2 + w), w: 0=q, 1=k
    const int w = bw & 1;
    const int h = (bw >> 1) & 15;
    const int b = bw >> 5;
    __shared__ float red[256];
    float mx = 0.f;
    for (int i = threadIdx.x; i < N_ * D_; i += 256) {
        int n = i >> 6, d = i & 63;
        float v = g_qkv[((size_t)(b * N_ + n)) * (3 * C_) + w * C_ + h * D_ + d];
        mx = fmaxf(mx, fabsf(v));
    }
    red[threadIdx.x] = mx;
    __syncthreads();
    for (int s = 128; s; s >>= 1) {
        if (threadIdx.x < s) red[threadIdx.x] = fmaxf(red[threadIdx.x], red[threadIdx.x + s]);
        __syncthreads();
    }
    if (threadIdx.x == 0) {
        float amax = fmaxf(red[0], 1e-12f);
        g_scale[bw]  = 448.f / amax;
        g_iscale[bw] = amax / 448.f;
    }
}

// ---------------------------------------------------------------------------
// fp8 e4m3 quantize-dequantize of Q and K in place (vectorized by float4)
// ---------------------------------------------------------------------------
__global__ void quant_kernel() {
    int gid = blockIdx.x * blockDim.x + threadIdx.x;
    if (gid >= B_ * N_ * 2 * (C_ / 4)) return;
    int c4 = (gid & 255) * 4;
    int w  = (gid >> 8) & 1;
    int n  = (gid >> 9) & 2047;
    int b  = gid >> 20;
    int h  = c4 >> 6;
    int si = (b * 16 + h) * 2 + w;
    float s  = g_scale[si];
    float is = g_iscale[si];
    size_t base = ((size_t)(b * N_ + n)) * (3 * C_) + w * C_ + c4;
    float4 v = *(float4*)&g_qkv[base];
    v.x = (float)__nv_fp8_e4m3(v.x * s) * is;
    v.y = (float)__nv_fp8_e4m3(v.y * s) * is;
    v.z = (float)__nv_fp8_e4m3(v.z * s) * is;
    v.w = (float)__nv_fp8_e4m3(v.w * s) * is;
    *(float4*)&g_qkv[base] = v;
}

// ---------------------------------------------------------------------------
// Causal flash attention fp32. Br=64 q-rows per block, Bc=32 k-cols per tile.
// ---------------------------------------------------------------------------
__global__ void flash_kernel() {
    const int qt = blockIdx.x, h = blockIdx.y, b = blockIdx.z;
    const int q0 = qt * 64;
    __shared__ float Qs[64][68];
    __shared__ float Ks[32][68];
    __shared__ float Vs[32][68];
    __shared__ float Ps[64][36];
    const int tid = threadIdx.x;

#pragma unroll
    for (int ll = 0; ll < 4; ll++) {
        int idx = tid + ll * 256;
        int r = idx >> 4, c4 = (idx & 15) * 4;
        *(float4*)&Qs[r][c4] =
            *(const float4*)&g_qkv[((size_t)(b * N_ + q0 + r)) * (3 * C_) + h * D_ + c4];
    }
    __syncthreads();

    const int r = tid >> 2, c = tid & 3;
    const int gq = q0 + r;
    float m = -INFINITY, l = 0.f;
    float o[16];
#pragma unroll
    for (int i = 0; i < 16; i++) o[i] = 0.f;

    for (int kt = 0; kt <= 2 * qt + 1; kt++) {
        const int k0 = kt * 32;
#pragma unroll
        for (int ll = 0; ll < 2; ll++) {
            int idx = tid + ll * 256;
            int rr = idx >> 4, c4 = (idx & 15) * 4;
            size_t g = ((size_t)(b * N_ + k0 + rr)) * (3 * C_) + C_ + h * D_ + c4;
            *(float4*)&Ks[rr][c4] = *(const float4*)&g_qkv[g];
            *(float4*)&Vs[rr][c4] = *(const float4*)&g_qkv[g + C_];
        }
        __syncthreads();

        float s[8];
#pragma unroll
        for (int j = 0; j < 8; j++) s[j] = 0.f;
#pragma unroll
        for (int d0 = 0; d0 < 64; d0 += 4) {
            float4 qv = *(float4*)&Qs[r][d0];
#pragma unroll
            for (int j = 0; j < 8; j++) {
                float4 kv = *(float4*)&Ks[c * 8 + j][d0];
                s[j] += qv.x * kv.x + qv.y * kv.y + qv.z * kv.z + qv.w * kv.w;
            }
        }
        const float sm = 0.125f;
#pragma unroll
        for (int j = 0; j < 8; j++) {
            int gk = k0 + c * 8 + j;
            s[j] = (gk <= gq) ? s[j] * sm : -1e30f;
        }
        float mloc = s[0];
#pragma unroll
        for (int j = 1; j < 8; j++) mloc = fmaxf(mloc, s[j]);
        mloc = fmaxf(mloc, __shfl_xor_sync(0xffffffffu, mloc, 1));
        mloc = fmaxf(mloc, __shfl_xor_sync(0xffffffffu, mloc, 2));
        float mnew = fmaxf(m, mloc);
        float fac = __expf(m - mnew);
        float psum = 0.f;
#pragma unroll
        for (int j = 0; j < 8; j++) { s[j] = __expf(s[j] - mnew); psum += s[j]; }
        psum += __shfl_xor_sync(0xffffffffu, psum, 1);
        psum += __shfl_xor_sync(0xffffffffu, psum, 2);
        l = l * fac + psum;
        m = mnew;
#pragma unroll
        for (int dd = 0; dd < 16; dd++) o[dd] *= fac;
#pragma unroll
        for (int j = 0; j < 8; j++) Ps[r][c * 8 + j] = s[j];
        __syncwarp();
#pragma unroll
        for (int j = 0; j < 32; j++) {
            float p = Ps[r][j];
            const float* vrow = &Vs[j][c * 16];
#pragma unroll
            for (int dd = 0; dd < 16; dd += 4) {
                float4 vv = *(const float4*)&vrow[dd];
                o[dd + 0] += p * vv.x; o[dd + 1] += p * vv.y;
                o[dd + 2] += p * vv.z; o[dd + 3] += p * vv.w;
            }
        }
        __syncthreads();
    }
    float inv = 1.f / l;
    size_t ob = ((size_t)(b * N_ + gq)) * C_ + h * D_ + c * 16;
#pragma unroll
    for (int dd = 0; dd < 16; dd += 4) {
        float4 v;
        v.x = o[dd] * inv; v.y = o[dd + 1] * inv; v.z = o[dd + 2] * inv; v.w = o[dd + 3] * inv;
        *(float4*)&g_att[ob + dd] = v;
    }
}

// ---------------------------------------------------------------------------
extern "C" void kernel_launch(void* const* d_in, const int* in_sizes, int n_in,
                              void* d_out, int out_size) {
    const float* x      = (const float*)d_in[0];   // [2,2048,1024]
    const float* w_qkv  = (const float*)d_in[1];   // [1024,3072]
    const float* w_proj = (const float*)d_in[2];   // [1024,1024]
    const float* b_proj = (const float*)d_in[3];   // [1024]
    float* out = (float*)d_out;                    // [2,2048,1024]

    float* qkv_ptr; cudaGetSymbolAddress((void**)&qkv_ptr, g_qkv);
    float* att_ptr; cudaGetSymbolAddress((void**)&att_ptr, g_att);

    // 1) QKV GEMM: [4096,1024] @ [1024,3072]  (3xTF32 tensor path)
    {
        dim3 grid(3 * C_ / 128, (B_ * N_) / 128);
        gemm_tf32x3<false><<<grid, 256>>>(x, w_qkv, nullptr, qkv_ptr, B_ * N_, 3 * C_, C_);
    }
    // 2) amax -> scales
    amax_kernel<<<64, 256>>>();
    // 3) fp8 quant-dequant of Q,K in place
    quant_kernel<<<(B_ * N_ * 2 * (C_ / 4) + 255) / 256, 256>>>();
    // 4) causal flash attention
    {
        dim3 grid(N_ / 64, H_, B_);
        flash_kernel<<<grid, 256>>>();
    }
    // 5) output projection + bias (3xTF32 tensor path)
    {
        dim3 grid(C_ / 128, (B_ * N_) / 128);
        gemm_tf32x3<true><<<grid, 256>>>(att_ptr, w_proj, b_proj, out, B_ * N_, C_, C_);
    }
}

// round 4
// speedup vs baseline: 3.9765x; 3.8680x over previous
#include <cuda_runtime.h>
#include <cuda_fp8.h>
#include <math.h>

#define B_ 2
#define N_ 2048
#define C_ 1024
#define H_ 16
#define D_ 64

// Scratch (allocation-free contract: __device__ globals)
__device__ float g_qkv[B_ * N_ * 3 * C_];            // [B,N,3,H,D] as [B*N, 3C]
__device__ float g_att[B_ * N_ * C_];                // attention output [B,N,C]
__device__ float g_scale[64];                        // 448/amax per (b,h,{q,k})
__device__ float g_iscale[64];                       // amax/448
__device__ unsigned char g_q8[B_ * H_ * N_ * D_];    // fp8 q, head-major [b,h,n,d]
__device__ unsigned char g_k8[B_ * H_ * N_ * D_];    // fp8 k, head-major

// ---------------------------------------------------------------------------
// MMA helpers
// ---------------------------------------------------------------------------
__device__ __forceinline__ unsigned f2tf(float x) {
    unsigned u;
    asm("cvt.rna.tf32.f32 %0, %1;" : "=r"(u) : "f"(x));
    return u;
}

__device__ __forceinline__ void mma_tf32(float* d, const unsigned* a, const unsigned* b) {
    asm volatile(
        "mma.sync.aligned.m16n8k8.row.col.f32.tf32.tf32.f32 "
        "{%0,%1,%2,%3},{%4,%5,%6,%7},{%8,%9},{%0,%1,%2,%3};"
        : "+f"(d[0]), "+f"(d[1]), "+f"(d[2]), "+f"(d[3])
        : "r"(a[0]), "r"(a[1]), "r"(a[2]), "r"(a[3]), "r"(b[0]), "r"(b[1]));
}

__device__ __forceinline__ void mma_e4m3(float* d, const unsigned* a, unsigned b0, unsigned b1) {
    asm volatile(
        "mma.sync.aligned.m16n8k32.row.col.f32.e4m3.e4m3.f32 "
        "{%0,%1,%2,%3},{%4,%5,%6,%7},{%8,%9},{%0,%1,%2,%3};"
        : "+f"(d[0]), "+f"(d[1]), "+f"(d[2]), "+f"(d[3])
        : "r"(a[0]), "r"(a[1]), "r"(a[2]), "r"(a[3]), "r"(b0), "r"(b1));
}

// ---------------------------------------------------------------------------
// 3xTF32 GEMM: C[M,N] = A[M,K] @ B[K,N] (+bias), near-fp32 accuracy.
// Block 128x128, 8 warps (warp tile 32x64), K-step 16.
// ---------------------------------------------------------------------------
template <bool BIAS>
__global__ void gemm_tf32x3(const float* __restrict__ A, const float* __restrict__ Bm,
                            const float* __restrict__ bias, float* __restrict__ Cm,
                            int M, int N, int K) {
    __shared__ float As[128 * 20];
    __shared__ float Bs[16 * 136];
    const int bm = blockIdx.y * 128;
    const int bn = blockIdx.x * 128;
    const int tid = threadIdx.x;
    const int wid = tid >> 5, lane = tid & 31;
    const int gid = lane >> 2, tig = lane & 3;
    const int wm = (wid & 3) * 32;
    const int wn = (wid >> 2) * 64;

    float acc[2][8][4];
#pragma unroll
    for (int i = 0; i < 2; i++)
#pragma unroll
        for (int j = 0; j < 8; j++)
#pragma unroll
            for (int t = 0; t < 4; t++) acc[i][j][t] = 0.f;

    for (int kt = 0; kt < K; kt += 16) {
        __syncthreads();
#pragma unroll
        for (int l = 0; l < 2; l++) {
            int idx = tid + l * 256;
            int r = idx >> 2, c4 = (idx & 3) * 4;
            float4 v = *(const float4*)&A[(size_t)(bm + r) * K + kt + c4];
            float* p = &As[r * 20 + c4];
            p[0] = v.x; p[1] = v.y; p[2] = v.z; p[3] = v.w;
        }
#pragma unroll
        for (int l = 0; l < 2; l++) {
            int idx = tid + l * 256;
            int r = idx >> 5, c4 = (idx & 31) * 4;
            float4 v = *(const float4*)&Bm[(size_t)(kt + r) * N + bn + c4];
            float* p = &Bs[r * 136 + c4];
            p[0] = v.x; p[1] = v.y; p[2] = v.z; p[3] = v.w;
        }
        __syncthreads();

#pragma unroll
        for (int k8 = 0; k8 < 16; k8 += 8) {
            unsigned Ah[2][4], Al[2][4], Bh[8][2], Bl[8][2];
#pragma unroll
            for (int mt = 0; mt < 2; mt++) {
                int r0 = wm + mt * 16 + gid;
                float x0 = As[r0 * 20 + k8 + tig];
                float x1 = As[(r0 + 8) * 20 + k8 + tig];
                float x2 = As[r0 * 20 + k8 + tig + 4];
                float x3 = As[(r0 + 8) * 20 + k8 + tig + 4];
                Ah[mt][0] = f2tf(x0); Al[mt][0] = f2tf(x0 - __uint_as_float(Ah[mt][0]));
                Ah[mt][1] = f2tf(x1); Al[mt][1] = f2tf(x1 - __uint_as_float(Ah[mt][1]));
                Ah[mt][2] = f2tf(x2); Al[mt][2] = f2tf(x2 - __uint_as_float(Ah[mt][2]));
                Ah[mt][3] = f2tf(x3); Al[mt][3] = f2tf(x3 - __uint_as_float(Ah[mt][3]));
            }
#pragma unroll
            for (int nt = 0; nt < 8; nt++) {
                int c0 = wn + nt * 8 + gid;
                float y0 = Bs[(k8 + tig) * 136 + c0];
                float y1 = Bs[(k8 + tig + 4) * 136 + c0];
                Bh[nt][0] = f2tf(y0); Bl[nt][0] = f2tf(y0 - __uint_as_float(Bh[nt][0]));
                Bh[nt][1] = f2tf(y1); Bl[nt][1] = f2tf(y1 - __uint_as_float(Bh[nt][1]));
            }
#pragma unroll
            for (int mt = 0; mt < 2; mt++)
#pragma unroll
                for (int nt = 0; nt < 8; nt++) {
                    mma_tf32(acc[mt][nt], Al[mt], Bh[nt]);
                    mma_tf32(acc[mt][nt], Ah[mt], Bl[nt]);
                    mma_tf32(acc[mt][nt], Ah[mt], Bh[nt]);
                }
        }
    }

#pragma unroll
    for (int mt = 0; mt < 2; mt++)
#pragma unroll
        for (int nt = 0; nt < 8; nt++) {
            int r = bm + wm + mt * 16 + gid;
            int c = bn + wn + nt * 8 + 2 * tig;
            float b0 = 0.f, b1 = 0.f;
            if (BIAS) { b0 = bias[c]; b1 = bias[c + 1]; }
            Cm[(size_t)r * N + c]           = acc[mt][nt][0] + b0;
            Cm[(size_t)r * N + c + 1]       = acc[mt][nt][1] + b1;
            Cm[(size_t)(r + 8) * N + c]     = acc[mt][nt][2] + b0;
            Cm[(size_t)(r + 8) * N + c + 1] = acc[mt][nt][3] + b1;
        }
}

// ---------------------------------------------------------------------------
// Per-(b,h,{q,k}) amax over the [N,D] slab -> scale / inv-scale
// ---------------------------------------------------------------------------
__global__ void amax_kernel() {
    const int bw = blockIdx.x;
    const int w = bw & 1;
    const int h = (bw >> 1) & 15;
    const int b = bw >> 5;
    __shared__ float red[256];
    float mx = 0.f;
    for (int i = threadIdx.x; i < N_ * D_; i += 256) {
        int n = i >> 6, d = i & 63;
        float v = g_qkv[((size_t)(b * N_ + n)) * (3 * C_) + w * C_ + h * D_ + d];
        mx = fmaxf(mx, fabsf(v));
    }
    red[threadIdx.x] = mx;
    __syncthreads();
    for (int s = 128; s; s >>= 1) {
        if (threadIdx.x < s) red[threadIdx.x] = fmaxf(red[threadIdx.x], red[threadIdx.x + s]);
        __syncthreads();
    }
    if (threadIdx.x == 0) {
        float amax = fmaxf(red[0], 1e-12f);
        g_scale[bw]  = 448.f / amax;
        g_iscale[bw] = amax / 448.f;
    }
}

// ---------------------------------------------------------------------------
// fp8 quantize Q and K into head-major byte arrays (scores use raw fp8 values;
// the iscale_q*iscale_k factor is applied after the MMA — exactly equivalent
// to reference dequant-then-multiply).
// ---------------------------------------------------------------------------
__global__ void quant_kernel() {
    int gid = blockIdx.x * blockDim.x + threadIdx.x;
    if (gid >= B_ * N_ * 2 * (C_ / 4)) return;
    int c4 = (gid & 255) * 4;
    int w  = (gid >> 8) & 1;
    int n  = (gid >> 9) & 2047;
    int b  = gid >> 20;
    int h  = c4 >> 6;
    int d  = c4 & 63;
    int si = (b * 16 + h) * 2 + w;
    float s = g_scale[si];
    size_t base = ((size_t)(b * N_ + n)) * (3 * C_) + w * C_ + c4;
    float4 v = *(const float4*)&g_qkv[base];
    unsigned u0 = __nv_cvt_float_to_fp8(v.x * s, __NV_SATFINITE, __NV_E4M3);
    unsigned u1 = __nv_cvt_float_to_fp8(v.y * s, __NV_SATFINITE, __NV_E4M3);
    unsigned u2 = __nv_cvt_float_to_fp8(v.z * s, __NV_SATFINITE, __NV_E4M3);
    unsigned u3 = __nv_cvt_float_to_fp8(v.w * s, __NV_SATFINITE, __NV_E4M3);
    unsigned word = u0 | (u1 << 8) | (u2 << 16) | (u3 << 24);
    unsigned char* dst = (w == 0) ? g_q8 : g_k8;
    *(unsigned*)&dst[((size_t)((b * 16 + h) * N_ + n)) * 64 + d] = word;
}

// ---------------------------------------------------------------------------
// Tensor-core causal flash attention.
// Block: 128 thr (4 warps). Br=Bc=64. QK^T in fp8 e4m3 mma (exact vs ref),
// PV in tf32 mma (~1e-4 rounding). Online softmax on fragments.
// ---------------------------------------------------------------------------
#define KSTR 17   // K8 tile row stride in 4-byte words (68B)
#define VSTR 72   // V  tile row stride in floats
#define PSTR 72   // P  tile row stride in floats

__global__ void flash_fp8() {
    const int qt = blockIdx.x, h = blockIdx.y, b = blockIdx.z;
    const int q0 = qt * 64;
    __shared__ unsigned Ks8[64 * KSTR];
    __shared__ float Vs[64 * VSTR];
    __shared__ float Ps[64 * PSTR];

    const int tid = threadIdx.x;
    const int w = tid >> 5, lane = tid & 31;
    const int gid = lane >> 2, tig = lane & 3;
    const int bh = b * H_ + h;
    const unsigned* q8 = (const unsigned*)(g_q8 + (size_t)bh * N_ * D_);
    const unsigned* k8 = (const unsigned*)(g_k8 + (size_t)bh * N_ * D_);
    const float sc = g_iscale[bh * 2 + 0] * g_iscale[bh * 2 + 1] * 0.125f;

    // Q fragments (persist whole kernel). a-frag for m16n8k32:
    // a0:(row gid, k 4t..) a1:(gid+8, 4t) a2:(gid, 16+4t) a3:(gid+8, 16+4t)
    const int r0 = q0 + w * 16 + gid;
    unsigned qa[2][4];
#pragma unroll
    for (int ks = 0; ks < 2; ks++) {
        qa[ks][0] = q8[r0 * 16 + tig + 8 * ks];
        qa[ks][1] = q8[(r0 + 8) * 16 + tig + 8 * ks];
        qa[ks][2] = q8[r0 * 16 + tig + 4 + 8 * ks];
        qa[ks][3] = q8[(r0 + 8) * 16 + tig + 4 + 8 * ks];
    }

    float m0 = -INFINITY, m1 = -INFINITY, l0 = 0.f, l1 = 0.f;
    float o[8][4];
#pragma unroll
    for (int nt = 0; nt < 8; nt++)
#pragma unroll
        for (int e = 0; e < 4; e++) o[nt][e] = 0.f;

    const int prow0 = (w * 16 + gid) * PSTR;
    const int prow1 = (w * 16 + gid + 8) * PSTR;

    for (int kt = 0; kt <= qt; kt++) {
        const int k0 = kt * 64;
        __syncthreads();
        // K8 tile: 64 rows x 16 words
#pragma unroll
        for (int i = tid; i < 64 * 16; i += 128) {
            int rr = i >> 4, wd = i & 15;
            Ks8[rr * KSTR + wd] = k8[(k0 + rr) * 16 + wd];
        }
        // V tile: 64 x 64, rounded to tf32 at load
#pragma unroll
        for (int i = tid; i < 64 * 16; i += 128) {
            int rr = i >> 4, c4 = (i & 15) * 4;
            float4 v = *(const float4*)&g_qkv[((size_t)(b * N_ + k0 + rr)) * (3 * C_) + 2 * C_ + h * D_ + c4];
            float* p = &Vs[rr * VSTR + c4];
            p[0] = __uint_as_float(f2tf(v.x));
            p[1] = __uint_as_float(f2tf(v.y));
            p[2] = __uint_as_float(f2tf(v.z));
            p[3] = __uint_as_float(f2tf(v.w));
        }
        __syncthreads();

        // S = q8 k8^T (fp8 mma), then scale + mask
        float s[8][4];
#pragma unroll
        for (int nt = 0; nt < 8; nt++) {
            s[nt][0] = s[nt][1] = s[nt][2] = s[nt][3] = 0.f;
            const int col = nt * 8 + gid;
            unsigned b0 = Ks8[col * KSTR + tig];
            unsigned b1 = Ks8[col * KSTR + tig + 4];
            mma_e4m3(s[nt], qa[0], b0, b1);
            unsigned b2 = Ks8[col * KSTR + tig + 8];
            unsigned b3 = Ks8[col * KSTR + tig + 12];
            mma_e4m3(s[nt], qa[1], b2, b3);
        }
        const bool diag = (kt == qt);
#pragma unroll
        for (int nt = 0; nt < 8; nt++) {
            s[nt][0] *= sc; s[nt][1] *= sc; s[nt][2] *= sc; s[nt][3] *= sc;
            if (diag) {
                int cl = nt * 8 + 2 * tig;
                int rl0 = w * 16 + gid, rl1 = rl0 + 8;
                if (cl > rl0)     s[nt][0] = -1e30f;
                if (cl + 1 > rl0) s[nt][1] = -1e30f;
                if (cl > rl1)     s[nt][2] = -1e30f;
                if (cl + 1 > rl1) s[nt][3] = -1e30f;
            }
        }
        // online softmax (rows gid and gid+8 of this warp)
        float mx0 = s[0][0], mx1 = s[0][2];
#pragma unroll
        for (int nt = 0; nt < 8; nt++) {
            mx0 = fmaxf(mx0, fmaxf(s[nt][0], s[nt][1]));
            mx1 = fmaxf(mx1, fmaxf(s[nt][2], s[nt][3]));
        }
        mx0 = fmaxf(mx0, __shfl_xor_sync(0xffffffffu, mx0, 1));
        mx0 = fmaxf(mx0, __shfl_xor_sync(0xffffffffu, mx0, 2));
        mx1 = fmaxf(mx1, __shfl_xor_sync(0xffffffffu, mx1, 1));
        mx1 = fmaxf(mx1, __shfl_xor_sync(0xffffffffu, mx1, 2));
        const float mn0 = fmaxf(m0, mx0), mn1 = fmaxf(m1, mx1);
        const float f0 = __expf(m0 - mn0), f1 = __expf(m1 - mn1);
        float sum0 = 0.f, sum1 = 0.f;
#pragma unroll
        for (int nt = 0; nt < 8; nt++) {
            float p0 = __expf(s[nt][0] - mn0);
            float p1 = __expf(s[nt][1] - mn0);
            float p2 = __expf(s[nt][2] - mn1);
            float p3 = __expf(s[nt][3] - mn1);
            sum0 += p0 + p1; sum1 += p2 + p3;
            float2* q = (float2*)&Ps[prow0 + nt * 8 + 2 * tig];
            q->x = __uint_as_float(f2tf(p0)); q->y = __uint_as_float(f2tf(p1));
            float2* r = (float2*)&Ps[prow1 + nt * 8 + 2 * tig];
            r->x = __uint_as_float(f2tf(p2)); r->y = __uint_as_float(f2tf(p3));
#pragma unroll
            for (int e = 0; e < 2; e++) { o[nt][e] *= f0; o[nt][e + 2] *= f1; }
        }
        sum0 += __shfl_xor_sync(0xffffffffu, sum0, 1);
        sum0 += __shfl_xor_sync(0xffffffffu, sum0, 2);
        sum1 += __shfl_xor_sync(0xffffffffu, sum1, 1);
        sum1 += __shfl_xor_sync(0xffffffffu, sum1, 2);
        l0 = l0 * f0 + sum0;
        l1 = l1 * f1 + sum1;
        m0 = mn0; m1 = mn1;
        __syncwarp();

        // O += P V (tf32 mma): A = P rows of this warp, B = V
#pragma unroll
        for (int k8t = 0; k8t < 8; k8t++) {
            unsigned a[4];
            a[0] = __float_as_uint(Ps[prow0 + k8t * 8 + tig]);
            a[1] = __float_as_uint(Ps[prow1 + k8t * 8 + tig]);
            a[2] = __float_as_uint(Ps[prow0 + k8t * 8 + tig + 4]);
            a[3] = __float_as_uint(Ps[prow1 + k8t * 8 + tig + 4]);
#pragma unroll
            for (int nt = 0; nt < 8; nt++) {
                unsigned bb[2];
                bb[0] = __float_as_uint(Vs[(k8t * 8 + tig) * VSTR + nt * 8 + gid]);
                bb[1] = __float_as_uint(Vs[(k8t * 8 + tig + 4) * VSTR + nt * 8 + gid]);
                mma_tf32(o[nt], a, bb);
            }
        }
    }

    // epilogue
    const float il0 = 1.f / l0, il1 = 1.f / l1;
#pragma unroll
    for (int nt = 0; nt < 8; nt++) {
        size_t c = h * D_ + nt * 8 + 2 * tig;
        float2 v0; v0.x = o[nt][0] * il0; v0.y = o[nt][1] * il0;
        float2 v1; v1.x = o[nt][2] * il1; v1.y = o[nt][3] * il1;
        *(float2*)&g_att[((size_t)(b * N_ + r0)) * C_ + c]     = v0;
        *(float2*)&g_att[((size_t)(b * N_ + r0 + 8)) * C_ + c] = v1;
    }
}

// ---------------------------------------------------------------------------
extern "C" void kernel_launch(void* const* d_in, const int* in_sizes, int n_in,
                              void* d_out, int out_size) {
    const float* x      = (const float*)d_in[0];   // [2,2048,1024]
    const float* w_qkv  = (const float*)d_in[1];   // [1024,3072]
    const float* w_proj = (const float*)d_in[2];   // [1024,1024]
    const float* b_proj = (const float*)d_in[3];   // [1024]
    float* out = (float*)d_out;                    // [2,2048,1024]

    float* qkv_ptr; cudaGetSymbolAddress((void**)&qkv_ptr, g_qkv);
    float* att_ptr; cudaGetSymbolAddress((void**)&att_ptr, g_att);

    // 1) QKV GEMM (3xTF32 tensor path)
    {
        dim3 grid(3 * C_ / 128, (B_ * N_) / 128);
        gemm_tf32x3<false><<<grid, 256>>>(x, w_qkv, nullptr, qkv_ptr, B_ * N_, 3 * C_, C_);
    }
    // 2) amax -> scales
    amax_kernel<<<64, 256>>>();
    // 3) fp8 quantize q,k into byte arrays
    quant_kernel<<<(B_ * N_ * 2 * (C_ / 4) + 255) / 256, 256>>>();
    // 4) tensor-core causal flash attention
    {
        dim3 grid(N_ / 64, H_, B_);
        flash_fp8<<<grid, 128>>>();
    }
    // 5) output projection + bias (3xTF32 tensor path)
    {
        dim3 grid(C_ / 128, (B_ * N_) / 128);
        gemm_tf32x3<true><<<grid, 256>>>(att_ptr, w_proj, b_proj, out, B_ * N_, C_, C_);
    }
}

// round 5
// speedup vs baseline: 4.6452x; 1.1682x over previous
#include <cuda_runtime.h>
#include <cuda_fp8.h>
#include <math.h>

#define B_ 2
#define N_ 2048
#define C_ 1024
#define H_ 16
#define D_ 64

// Scratch (allocation-free contract: __device__ globals)
__device__ float g_qkv[B_ * N_ * 3 * C_];            // [B,N,3,H,D] as [B*N, 3C]
__device__ float g_att[B_ * N_ * C_];                // attention output [B,N,C]
__device__ float g_scale[64];                        // 448/amax per (b,h,{q,k})
__device__ float g_iscale[64];                       // amax/448
__device__ float g_part[64 * 8];                     // partial amax
__device__ unsigned char g_q8[B_ * H_ * N_ * D_];    // fp8 q, head-major [b,h,n,d]
__device__ unsigned char g_k8[B_ * H_ * N_ * D_];    // fp8 k, head-major

// ---------------------------------------------------------------------------
// helpers
// ---------------------------------------------------------------------------
__device__ __forceinline__ unsigned f2tf(float x) {
    unsigned u;
    asm("cvt.rna.tf32.f32 %0, %1;" : "=r"(u) : "f"(x));
    return u;
}

__device__ __forceinline__ void mma_tf32(float* d, const unsigned* a, const unsigned* b) {
    asm volatile(
        "mma.sync.aligned.m16n8k8.row.col.f32.tf32.tf32.f32 "
        "{%0,%1,%2,%3},{%4,%5,%6,%7},{%8,%9},{%0,%1,%2,%3};"
        : "+f"(d[0]), "+f"(d[1]), "+f"(d[2]), "+f"(d[3])
        : "r"(a[0]), "r"(a[1]), "r"(a[2]), "r"(a[3]), "r"(b[0]), "r"(b[1]));
}

__device__ __forceinline__ void mma_e4m3(float* d, const unsigned* a, unsigned b0, unsigned b1) {
    asm volatile(
        "mma.sync.aligned.m16n8k32.row.col.f32.e4m3.e4m3.f32 "
        "{%0,%1,%2,%3},{%4,%5,%6,%7},{%8,%9},{%0,%1,%2,%3};"
        : "+f"(d[0]), "+f"(d[1]), "+f"(d[2]), "+f"(d[3])
        : "r"(a[0]), "r"(a[1]), "r"(a[2]), "r"(a[3]), "r"(b0), "r"(b1));
}

__device__ __forceinline__ void cp16(void* smem, const void* gmem) {
    unsigned s = (unsigned)__cvta_generic_to_shared(smem);
    asm volatile("cp.async.cg.shared.global [%0], [%1], 16;" :: "r"(s), "l"(gmem));
}
#define CP_COMMIT asm volatile("cp.async.commit_group;")
#define CP_WAIT0  asm volatile("cp.async.wait_group 0;")

// ---------------------------------------------------------------------------
// 3xTF32 GEMM, cp.async double-buffered. Block 128x128, 8 warps, K-step 16.
// ---------------------------------------------------------------------------
template <bool BIAS>
__global__ void gemm_tf32x3(const float* __restrict__ A, const float* __restrict__ Bm,
                            const float* __restrict__ bias, float* __restrict__ Cm,
                            int M, int N, int K) {
    __shared__ float As[2][128 * 20];
    __shared__ float Bs[2][16 * 136];
    const int bm = blockIdx.y * 128;
    const int bn = blockIdx.x * 128;
    const int tid = threadIdx.x;
    const int wid = tid >> 5, lane = tid & 31;
    const int gid = lane >> 2, tig = lane & 3;
    const int wm = (wid & 3) * 32;
    const int wn = (wid >> 2) * 64;

    // per-thread load coords
    const int ar = tid >> 2, ac = (tid & 3) * 4;        // A: rows ar, ar+64
    const int br = tid >> 5, bc = (tid & 31) * 4;       // B: rows br, br+8

    float acc[2][8][4];
#pragma unroll
    for (int i = 0; i < 2; i++)
#pragma unroll
        for (int j = 0; j < 8; j++)
#pragma unroll
            for (int t = 0; t < 4; t++) acc[i][j][t] = 0.f;

    auto issue = [&](int kt, int buf) {
        cp16(&As[buf][ar * 20 + ac],        &A[(size_t)(bm + ar) * K + kt + ac]);
        cp16(&As[buf][(ar + 64) * 20 + ac], &A[(size_t)(bm + ar + 64) * K + kt + ac]);
        cp16(&Bs[buf][br * 136 + bc],       &Bm[(size_t)(kt + br) * N + bn + bc]);
        cp16(&Bs[buf][(br + 8) * 136 + bc], &Bm[(size_t)(kt + br + 8) * N + bn + bc]);
    };

    issue(0, 0);
    CP_COMMIT;
    CP_WAIT0;
    __syncthreads();

    int buf = 0;
    for (int kt = 0; kt < K; kt += 16) {
        if (kt + 16 < K) { issue(kt + 16, buf ^ 1); }
        CP_COMMIT;

#pragma unroll
        for (int k8 = 0; k8 < 16; k8 += 8) {
            unsigned Ah[2][4], Al[2][4], Bh[8][2], Bl[8][2];
#pragma unroll
            for (int mt = 0; mt < 2; mt++) {
                int r0 = wm + mt * 16 + gid;
                float x0 = As[buf][r0 * 20 + k8 + tig];
                float x1 = As[buf][(r0 + 8) * 20 + k8 + tig];
                float x2 = As[buf][r0 * 20 + k8 + tig + 4];
                float x3 = As[buf][(r0 + 8) * 20 + k8 + tig + 4];
                Ah[mt][0] = f2tf(x0); Al[mt][0] = f2tf(x0 - __uint_as_float(Ah[mt][0]));
                Ah[mt][1] = f2tf(x1); Al[mt][1] = f2tf(x1 - __uint_as_float(Ah[mt][1]));
                Ah[mt][2] = f2tf(x2); Al[mt][2] = f2tf(x2 - __uint_as_float(Ah[mt][2]));
                Ah[mt][3] = f2tf(x3); Al[mt][3] = f2tf(x3 - __uint_as_float(Ah[mt][3]));
            }
#pragma unroll
            for (int nt = 0; nt < 8; nt++) {
                int c0 = wn + nt * 8 + gid;
                float y0 = Bs[buf][(k8 + tig) * 136 + c0];
                float y1 = Bs[buf][(k8 + tig + 4) * 136 + c0];
                Bh[nt][0] = f2tf(y0); Bl[nt][0] = f2tf(y0 - __uint_as_float(Bh[nt][0]));
                Bh[nt][1] = f2tf(y1); Bl[nt][1] = f2tf(y1 - __uint_as_float(Bh[nt][1]));
            }
#pragma unroll
            for (int mt = 0; mt < 2; mt++)
#pragma unroll
                for (int nt = 0; nt < 8; nt++) {
                    mma_tf32(acc[mt][nt], Al[mt], Bh[nt]);
                    mma_tf32(acc[mt][nt], Ah[mt], Bl[nt]);
                    mma_tf32(acc[mt][nt], Ah[mt], Bh[nt]);
                }
        }
        CP_WAIT0;
        __syncthreads();
        buf ^= 1;
    }

#pragma unroll
    for (int mt = 0; mt < 2; mt++)
#pragma unroll
        for (int nt = 0; nt < 8; nt++) {
            int r = bm + wm + mt * 16 + gid;
            int c = bn + wn + nt * 8 + 2 * tig;
            float b0 = 0.f, b1 = 0.f;
            if (BIAS) { b0 = bias[c]; b1 = bias[c + 1]; }
            Cm[(size_t)r * N + c]           = acc[mt][nt][0] + b0;
            Cm[(size_t)r * N + c + 1]       = acc[mt][nt][1] + b1;
            Cm[(size_t)(r + 8) * N + c]     = acc[mt][nt][2] + b0;
            Cm[(size_t)(r + 8) * N + c + 1] = acc[mt][nt][3] + b1;
        }
}

// ---------------------------------------------------------------------------
// amax: two-stage. Stage 1: 64x8 blocks, each reduces 256 rows. Stage 2: finalize.
// ---------------------------------------------------------------------------
__global__ void amax_part() {
    const int part = blockIdx.x;         // 0..7
    const int bw = blockIdx.y;           // 0..63: ((b*16+h)*2 + w)
    const int w = bw & 1;
    const int h = (bw >> 1) & 15;
    const int b = bw >> 5;
    __shared__ float red[256];
    float mx = 0.f;
    const int n0 = part * (N_ / 8);
    for (int i = threadIdx.x; i < (N_ / 8) * D_; i += 256) {
        int n = n0 + (i >> 6), d = i & 63;
        float v = g_qkv[((size_t)(b * N_ + n)) * (3 * C_) + w * C_ + h * D_ + d];
        mx = fmaxf(mx, fabsf(v));
    }
    red[threadIdx.x] = mx;
    __syncthreads();
    for (int s = 128; s; s >>= 1) {
        if (threadIdx.x < s) red[threadIdx.x] = fmaxf(red[threadIdx.x], red[threadIdx.x + s]);
        __syncthreads();
    }
    if (threadIdx.x == 0) g_part[bw * 8 + part] = red[0];
}

__global__ void amax_fin() {
    int bw = threadIdx.x;                // 0..63
    float mx = 0.f;
#pragma unroll
    for (int p = 0; p < 8; p++) mx = fmaxf(mx, g_part[bw * 8 + p]);
    float amax = fmaxf(mx, 1e-12f);
    g_scale[bw]  = 448.f / amax;
    g_iscale[bw] = amax / 448.f;
}

// ---------------------------------------------------------------------------
// fp8 quantize Q,K into head-major byte arrays
// ---------------------------------------------------------------------------
__global__ void quant_kernel() {
    int gid = blockIdx.x * blockDim.x + threadIdx.x;
    if (gid >= B_ * N_ * 2 * (C_ / 4)) return;
    int c4 = (gid & 255) * 4;
    int w  = (gid >> 8) & 1;
    int n  = (gid >> 9) & 2047;
    int b  = gid >> 20;
    int h  = c4 >> 6;
    int d  = c4 & 63;
    int si = (b * 16 + h) * 2 + w;
    float s = g_scale[si];
    size_t base = ((size_t)(b * N_ + n)) * (3 * C_) + w * C_ + c4;
    float4 v = *(const float4*)&g_qkv[base];
    unsigned u0 = __nv_cvt_float_to_fp8(v.x * s, __NV_SATFINITE, __NV_E4M3);
    unsigned u1 = __nv_cvt_float_to_fp8(v.y * s, __NV_SATFINITE, __NV_E4M3);
    unsigned u2 = __nv_cvt_float_to_fp8(v.z * s, __NV_SATFINITE, __NV_E4M3);
    unsigned u3 = __nv_cvt_float_to_fp8(v.w * s, __NV_SATFINITE, __NV_E4M3);
    unsigned word = u0 | (u1 << 8) | (u2 << 16) | (u3 << 24);
    unsigned char* dst = (w == 0) ? g_q8 : g_k8;
    *(unsigned*)&dst[((size_t)((b * 16 + h) * N_ + n)) * 64 + d] = word;
}

// ---------------------------------------------------------------------------
// Tensor-core causal flash attention, work-balanced: each block processes
// q-tiles {p, 31-p} -> exactly 33 k-tile iterations per block.
// ---------------------------------------------------------------------------
#define KSTR 17   // K8 tile row stride in 4-byte words (68B)
#define VSTR 72   // V  tile row stride in floats
#define PSTR 72   // P  tile row stride in floats

__global__ void flash_fp8() {
    const int pid = blockIdx.x, h = blockIdx.y, b = blockIdx.z;
    __shared__ unsigned Ks8[64 * KSTR];
    __shared__ float Vs[64 * VSTR];
    __shared__ float Ps[64 * PSTR];

    const int tid = threadIdx.x;
    const int w = tid >> 5, lane = tid & 31;
    const int gid = lane >> 2, tig = lane & 3;
    const int bh = b * H_ + h;
    const unsigned* q8 = (const unsigned*)(g_q8 + (size_t)bh * N_ * D_);
    const unsigned* k8 = (const unsigned*)(g_k8 + (size_t)bh * N_ * D_);
    const float sc = g_iscale[bh * 2 + 0] * g_iscale[bh * 2 + 1] * 0.125f;

    const int prow0 = (w * 16 + gid) * PSTR;
    const int prow1 = (w * 16 + gid + 8) * PSTR;

    for (int rep = 0; rep < 2; rep++) {
        const int qt = rep ? (N_ / 64 - 1 - pid) : pid;
        const int q0 = qt * 64;
        const int r0 = q0 + w * 16 + gid;

        unsigned qa[2][4];
#pragma unroll
        for (int ks = 0; ks < 2; ks++) {
            qa[ks][0] = q8[r0 * 16 + tig + 8 * ks];
            qa[ks][1] = q8[(r0 + 8) * 16 + tig + 8 * ks];
            qa[ks][2] = q8[r0 * 16 + tig + 4 + 8 * ks];
            qa[ks][3] = q8[(r0 + 8) * 16 + tig + 4 + 8 * ks];
        }

        float m0 = -INFINITY, m1 = -INFINITY, l0 = 0.f, l1 = 0.f;
        float o[8][4];
#pragma unroll
        for (int nt = 0; nt < 8; nt++)
#pragma unroll
            for (int e = 0; e < 4; e++) o[nt][e] = 0.f;

        for (int kt = 0; kt <= qt; kt++) {
            const int k0 = kt * 64;
            __syncthreads();
#pragma unroll
            for (int i = tid; i < 64 * 16; i += 128) {
                int rr = i >> 4, wd = i & 15;
                Ks8[rr * KSTR + wd] = k8[(k0 + rr) * 16 + wd];
            }
#pragma unroll
            for (int i = tid; i < 64 * 16; i += 128) {
                int rr = i >> 4, c4 = (i & 15) * 4;
                float4 v = *(const float4*)&g_qkv[((size_t)(b * N_ + k0 + rr)) * (3 * C_) + 2 * C_ + h * D_ + c4];
                float* p = &Vs[rr * VSTR + c4];
                p[0] = __uint_as_float(f2tf(v.x));
                p[1] = __uint_as_float(f2tf(v.y));
                p[2] = __uint_as_float(f2tf(v.z));
                p[3] = __uint_as_float(f2tf(v.w));
            }
            __syncthreads();

            float s[8][4];
#pragma unroll
            for (int nt = 0; nt < 8; nt++) {
                s[nt][0] = s[nt][1] = s[nt][2] = s[nt][3] = 0.f;
                const int col = nt * 8 + gid;
                unsigned b0 = Ks8[col * KSTR + tig];
                unsigned b1 = Ks8[col * KSTR + tig + 4];
                mma_e4m3(s[nt], qa[0], b0, b1);
                unsigned b2 = Ks8[col * KSTR + tig + 8];
                unsigned b3 = Ks8[col * KSTR + tig + 12];
                mma_e4m3(s[nt], qa[1], b2, b3);
            }
            const bool diag = (kt == qt);
#pragma unroll
            for (int nt = 0; nt < 8; nt++) {
                s[nt][0] *= sc; s[nt][1] *= sc; s[nt][2] *= sc; s[nt][3] *= sc;
                if (diag) {
                    int cl = nt * 8 + 2 * tig;
                    int rl0 = w * 16 + gid, rl1 = rl0 + 8;
                    if (cl > rl0)     s[nt][0] = -1e30f;
                    if (cl + 1 > rl0) s[nt][1] = -1e30f;
                    if (cl > rl1)     s[nt][2] = -1e30f;
                    if (cl + 1 > rl1) s[nt][3] = -1e30f;
                }
            }
            float mx0 = s[0][0], mx1 = s[0][2];
#pragma unroll
            for (int nt = 0; nt < 8; nt++) {
                mx0 = fmaxf(mx0, fmaxf(s[nt][0], s[nt][1]));
                mx1 = fmaxf(mx1, fmaxf(s[nt][2], s[nt][3]));
            }
            mx0 = fmaxf(mx0, __shfl_xor_sync(0xffffffffu, mx0, 1));
            mx0 = fmaxf(mx0, __shfl_xor_sync(0xffffffffu, mx0, 2));
            mx1 = fmaxf(mx1, __shfl_xor_sync(0xffffffffu, mx1, 1));
            mx1 = fmaxf(mx1, __shfl_xor_sync(0xffffffffu, mx1, 2));
            const float mn0 = fmaxf(m0, mx0), mn1 = fmaxf(m1, mx1);
            const float f0 = __expf(m0 - mn0), f1 = __expf(m1 - mn1);
            float sum0 = 0.f, sum1 = 0.f;
#pragma unroll
            for (int nt = 0; nt < 8; nt++) {
                float p0 = __expf(s[nt][0] - mn0);
                float p1 = __expf(s[nt][1] - mn0);
                float p2 = __expf(s[nt][2] - mn1);
                float p3 = __expf(s[nt][3] - mn1);
                sum0 += p0 + p1; sum1 += p2 + p3;
                float2* q = (float2*)&Ps[prow0 + nt * 8 + 2 * tig];
                q->x = __uint_as_float(f2tf(p0)); q->y = __uint_as_float(f2tf(p1));
                float2* r = (float2*)&Ps[prow1 + nt * 8 + 2 * tig];
                r->x = __uint_as_float(f2tf(p2)); r->y = __uint_as_float(f2tf(p3));
#pragma unroll
                for (int e = 0; e < 2; e++) { o[nt][e] *= f0; o[nt][e + 2] *= f1; }
            }
            sum0 += __shfl_xor_sync(0xffffffffu, sum0, 1);
            sum0 += __shfl_xor_sync(0xffffffffu, sum0, 2);
            sum1 += __shfl_xor_sync(0xffffffffu, sum1, 1);
            sum1 += __shfl_xor_sync(0xffffffffu, sum1, 2);
            l0 = l0 * f0 + sum0;
            l1 = l1 * f1 + sum1;
            m0 = mn0; m1 = mn1;
            __syncwarp();

#pragma unroll
            for (int k8t = 0; k8t < 8; k8t++) {
                unsigned a[4];
                a[0] = __float_as_uint(Ps[prow0 + k8t * 8 + tig]);
                a[1] = __float_as_uint(Ps[prow1 + k8t * 8 + tig]);
                a[2] = __float_as_uint(Ps[prow0 + k8t * 8 + tig + 4]);
                a[3] = __float_as_uint(Ps[prow1 + k8t * 8 + tig + 4]);
#pragma unroll
                for (int nt = 0; nt < 8; nt++) {
                    unsigned bb[2];
                    bb[0] = __float_as_uint(Vs[(k8t * 8 + tig) * VSTR + nt * 8 + gid]);
                    bb[1] = __float_as_uint(Vs[(k8t * 8 + tig + 4) * VSTR + nt * 8 + gid]);
                    mma_tf32(o[nt], a, bb);
                }
            }
        }

        const float il0 = 1.f / l0, il1 = 1.f / l1;
#pragma unroll
        for (int nt = 0; nt < 8; nt++) {
            size_t c = h * D_ + nt * 8 + 2 * tig;
            float2 v0; v0.x = o[nt][0] * il0; v0.y = o[nt][1] * il0;
            float2 v1; v1.x = o[nt][2] * il1; v1.y = o[nt][3] * il1;
            *(float2*)&g_att[((size_t)(b * N_ + r0)) * C_ + c]     = v0;
            *(float2*)&g_att[((size_t)(b * N_ + r0 + 8)) * C_ + c] = v1;
        }
    }
}

// ---------------------------------------------------------------------------
extern "C" void kernel_launch(void* const* d_in, const int* in_sizes, int n_in,
                              void* d_out, int out_size) {
    const float* x      = (const float*)d_in[0];   // [2,2048,1024]
    const float* w_qkv  = (const float*)d_in[1];   // [1024,3072]
    const float* w_proj = (const float*)d_in[2];   // [1024,1024]
    const float* b_proj = (const float*)d_in[3];   // [1024]
    float* out = (float*)d_out;                    // [2,2048,1024]

    float* qkv_ptr; cudaGetSymbolAddress((void**)&qkv_ptr, g_qkv);
    float* att_ptr; cudaGetSymbolAddress((void**)&att_ptr, g_att);

    // 1) QKV GEMM (3xTF32, cp.async pipelined)
    {
        dim3 grid(3 * C_ / 128, (B_ * N_) / 128);
        gemm_tf32x3<false><<<grid, 256>>>(x, w_qkv, nullptr, qkv_ptr, B_ * N_, 3 * C_, C_);
    }
    // 2) amax -> scales (two-stage)
    {
        dim3 grid(8, 64);
        amax_part<<<grid, 256>>>();
        amax_fin<<<1, 64>>>();
    }
    // 3) fp8 quantize q,k
    quant_kernel<<<(B_ * N_ * 2 * (C_ / 4) + 255) / 256, 256>>>();
    // 4) tensor-core causal flash attention (work-balanced pairs)
    {
        dim3 grid(N_ / 128, H_, B_);
        flash_fp8<<<grid, 128>>>();
    }
    // 5) output projection + bias (3xTF32, cp.async pipelined)
    {
        dim3 grid(C_ / 128, (B_ * N_) / 128);
        gemm_tf32x3<true><<<grid, 256>>>(att_ptr, w_proj, b_proj, out, B_ * N_, C_, C_);
    }
}

// round 7
// speedup vs baseline: 6.7890x; 1.4615x over previous
#include <cuda_runtime.h>
#include <cuda_fp16.h>
#include <cuda_fp8.h>
#include <math.h>

#define B_ 2
#define N_ 2048
#define C_ 1024
#define H_ 16
#define D_ 64

// Scratch (allocation-free contract: __device__ globals)
__device__ float g_qkv[B_ * N_ * 3 * C_];            // [B,N,3,H,D] as [B*N, 3C]
__device__ float g_scale[64];                        // 448/amax per (b,h,{q,k})
__device__ float g_iscale[64];                       // amax/448
__device__ float g_part[64 * 8];                     // partial amax
__device__ unsigned char g_q8[B_ * H_ * N_ * D_];    // fp8 q, head-major [b,h,n,d]
__device__ unsigned char g_k8[B_ * H_ * N_ * D_];    // fp8 k, head-major
// fp16 hi/lo splits
__device__ __half g_xh[B_ * N_ * C_];
__device__ __half g_xl[B_ * N_ * C_];
__device__ __half g_wqh[C_ * 3 * C_];
__device__ __half g_wql[C_ * 3 * C_];
__device__ __half g_wph[C_ * C_];
__device__ __half g_wpl[C_ * C_];
__device__ __half g_atth[B_ * N_ * C_];
__device__ __half g_attl[B_ * N_ * C_];

struct alignas(8) HH { __half2 a, b; };

// ---------------------------------------------------------------------------
// helpers
// ---------------------------------------------------------------------------
__device__ __forceinline__ void mma_f16(float* d, const unsigned* a, unsigned b0, unsigned b1) {
    asm volatile(
        "mma.sync.aligned.m16n8k16.row.col.f32.f16.f16.f32 "
        "{%0,%1,%2,%3},{%4,%5,%6,%7},{%8,%9},{%0,%1,%2,%3};"
        : "+f"(d[0]), "+f"(d[1]), "+f"(d[2]), "+f"(d[3])
        : "r"(a[0]), "r"(a[1]), "r"(a[2]), "r"(a[3]), "r"(b0), "r"(b1));
}

__device__ __forceinline__ void mma_e4m3(float* d, const unsigned* a, unsigned b0, unsigned b1) {
    asm volatile(
        "mma.sync.aligned.m16n8k32.row.col.f32.e4m3.e4m3.f32 "
        "{%0,%1,%2,%3},{%4,%5,%6,%7},{%8,%9},{%0,%1,%2,%3};"
        : "+f"(d[0]), "+f"(d[1]), "+f"(d[2]), "+f"(d[3])
        : "r"(a[0]), "r"(a[1]), "r"(a[2]), "r"(a[3]), "r"(b0), "r"(b1));
}

__device__ __forceinline__ void ldsm_x2t(unsigned& r0, unsigned& r1, const void* p) {
    unsigned s = (unsigned)__cvta_generic_to_shared(p);
    asm volatile("ldmatrix.sync.aligned.m8n8.x2.trans.shared.b16 {%0,%1}, [%2];"
                 : "=r"(r0), "=r"(r1) : "r"(s));
}

__device__ __forceinline__ void cp16(void* smem, const void* gmem) {
    unsigned s = (unsigned)__cvta_generic_to_shared(smem);
    asm volatile("cp.async.cg.shared.global [%0], [%1], 16;" :: "r"(s), "l"(gmem));
}
#define CP_COMMIT asm volatile("cp.async.commit_group;")
#define CP_WAIT0  asm volatile("cp.async.wait_group 0;")

// ---------------------------------------------------------------------------
// fp32 -> fp16 hi/lo split (elementwise), vectorized by 4
// ---------------------------------------------------------------------------
__global__ void prep_split(const float* __restrict__ src, __half* __restrict__ hi,
                           __half* __restrict__ lo, int n4) {
    int i = blockIdx.x * blockDim.x + threadIdx.x;
    if (i >= n4) return;
    float4 v = ((const float4*)src)[i];
    __half h0 = __float2half_rn(v.x); float r0 = v.x - __half2float(h0);
    __half h1 = __float2half_rn(v.y); float r1 = v.y - __half2float(h1);
    __half h2 = __float2half_rn(v.z); float r2 = v.z - __half2float(h2);
    __half h3 = __float2half_rn(v.w); float r3 = v.w - __half2float(h3);
    HH hh; hh.a = __halves2half2(h0, h1); hh.b = __halves2half2(h2, h3);
    *(HH*)&hi[(size_t)i * 4] = hh;
    HH ll;
    ll.a = __halves2half2(__float2half_rn(r0), __float2half_rn(r1));
    ll.b = __halves2half2(__float2half_rn(r2), __float2half_rn(r3));
    *(HH*)&lo[(size_t)i * 4] = ll;
}

// ---------------------------------------------------------------------------
// fp16x3 GEMM: C = A@B (+bias), near-fp32 accuracy (AhBh + AhBl + AlBh).
// A hi/lo [M][K] halfs, B hi/lo [K][N] halfs. Block 128x128, 8 warps, K-step 16.
// cp.async double-buffered. B-fragments via ldmatrix.x2.trans.
// ---------------------------------------------------------------------------
template <bool BIAS>
__global__ void gemm_f16x3(const __half* __restrict__ Ahp, const __half* __restrict__ Alp,
                           const __half* __restrict__ Bhp, const __half* __restrict__ Blp,
                           const float* __restrict__ bias, float* __restrict__ Cm,
                           int M, int N, int K) {
    __shared__ __half As_h[2][128 * 24], As_l[2][128 * 24];
    __shared__ __half Bs_h[2][16 * 136], Bs_l[2][16 * 136];
    const int bm = blockIdx.y * 128;
    const int bn = blockIdx.x * 128;
    const int tid = threadIdx.x;
    const int wid = tid >> 5, lane = tid & 31;
    const int gid = lane >> 2, tig = lane & 3;
    const int wm = (wid & 3) * 32;
    const int wn = (wid >> 2) * 64;

    const int arow = tid >> 1, ach = (tid & 1) * 8;
    const int brow = tid >> 4, bch = (tid & 15) * 8;

    float acc[2][8][4];
#pragma unroll
    for (int i = 0; i < 2; i++)
#pragma unroll
        for (int j = 0; j < 8; j++)
#pragma unroll
            for (int t = 0; t < 4; t++) acc[i][j][t] = 0.f;

    auto issue = [&](int kt, int buf) {
        cp16(&As_h[buf][arow * 24 + ach], &Ahp[(size_t)(bm + arow) * K + kt + ach]);
        cp16(&As_l[buf][arow * 24 + ach], &Alp[(size_t)(bm + arow) * K + kt + ach]);
        cp16(&Bs_h[buf][brow * 136 + bch], &Bhp[(size_t)(kt + brow) * N + bn + bch]);
        cp16(&Bs_l[buf][brow * 136 + bch], &Blp[(size_t)(kt + brow) * N + bn + bch]);
    };

    issue(0, 0);
    CP_COMMIT;
    CP_WAIT0;
    __syncthreads();

    int buf = 0;
    for (int kt = 0; kt < K; kt += 16) {
        if (kt + 16 < K) issue(kt + 16, buf ^ 1);
        CP_COMMIT;

        const unsigned* awh = (const unsigned*)As_h[buf];
        const unsigned* awl = (const unsigned*)As_l[buf];
        unsigned Af[2][4], Alf[2][4];
#pragma unroll
        for (int mt = 0; mt < 2; mt++) {
            int r0 = wm + mt * 16 + gid;
            Af[mt][0]  = awh[r0 * 12 + tig];
            Af[mt][1]  = awh[(r0 + 8) * 12 + tig];
            Af[mt][2]  = awh[r0 * 12 + tig + 4];
            Af[mt][3]  = awh[(r0 + 8) * 12 + tig + 4];
            Alf[mt][0] = awl[r0 * 12 + tig];
            Alf[mt][1] = awl[(r0 + 8) * 12 + tig];
            Alf[mt][2] = awl[r0 * 12 + tig + 4];
            Alf[mt][3] = awl[(r0 + 8) * 12 + tig + 4];
        }
#pragma unroll
        for (int nt = 0; nt < 8; nt++) {
            unsigned bh0, bh1, bl0, bl1;
            ldsm_x2t(bh0, bh1, &Bs_h[buf][(lane & 15) * 136 + wn + nt * 8]);
            ldsm_x2t(bl0, bl1, &Bs_l[buf][(lane & 15) * 136 + wn + nt * 8]);
#pragma unroll
            for (int mt = 0; mt < 2; mt++) {
                mma_f16(acc[mt][nt], Af[mt], bh0, bh1);
                mma_f16(acc[mt][nt], Af[mt], bl0, bl1);
                mma_f16(acc[mt][nt], Alf[mt], bh0, bh1);
            }
        }
        CP_WAIT0;
        __syncthreads();
        buf ^= 1;
    }

#pragma unroll
    for (int mt = 0; mt < 2; mt++)
#pragma unroll
        for (int nt = 0; nt < 8; nt++) {
            int r = bm + wm + mt * 16 + gid;
            int c = bn + wn + nt * 8 + 2 * tig;
            float b0 = 0.f, b1 = 0.f;
            if (BIAS) { b0 = bias[c]; b1 = bias[c + 1]; }
            Cm[(size_t)r * N + c]           = acc[mt][nt][0] + b0;
            Cm[(size_t)r * N + c + 1]       = acc[mt][nt][1] + b1;
            Cm[(size_t)(r + 8) * N + c]     = acc[mt][nt][2] + b0;
            Cm[(size_t)(r + 8) * N + c + 1] = acc[mt][nt][3] + b1;
        }
}

// ---------------------------------------------------------------------------
// amax: two-stage
// ---------------------------------------------------------------------------
__global__ void amax_part() {
    const int part = blockIdx.x;
    const int bw = blockIdx.y;
    const int w = bw & 1;
    const int h = (bw >> 1) & 15;
    const int b = bw >> 5;
    __shared__ float red[256];
    float mx = 0.f;
    const int n0 = part * (N_ / 8);
    for (int i = threadIdx.x; i < (N_ / 8) * D_; i += 256) {
        int n = n0 + (i >> 6), d = i & 63;
        float v = g_qkv[((size_t)(b * N_ + n)) * (3 * C_) + w * C_ + h * D_ + d];
        mx = fmaxf(mx, fabsf(v));
    }
    red[threadIdx.x] = mx;
    __syncthreads();
    for (int s = 128; s; s >>= 1) {
        if (threadIdx.x < s) red[threadIdx.x] = fmaxf(red[threadIdx.x], red[threadIdx.x + s]);
        __syncthreads();
    }
    if (threadIdx.x == 0) g_part[bw * 8 + part] = red[0];
}

__global__ void amax_fin() {
    int bw = threadIdx.x;
    float mx = 0.f;
#pragma unroll
    for (int p = 0; p < 8; p++) mx = fmaxf(mx, g_part[bw * 8 + p]);
    float amax = fmaxf(mx, 1e-12f);
    g_scale[bw]  = 448.f / amax;
    g_iscale[bw] = amax / 448.f;
}

// ---------------------------------------------------------------------------
// fp8 quantize Q,K into head-major byte arrays
// ---------------------------------------------------------------------------
__global__ void quant_kernel() {
    int gid = blockIdx.x * blockDim.x + threadIdx.x;
    if (gid >= B_ * N_ * 2 * (C_ / 4)) return;
    int c4 = (gid & 255) * 4;
    int w  = (gid >> 8) & 1;
    int n  = (gid >> 9) & 2047;
    int b  = gid >> 20;
    int h  = c4 >> 6;
    int d  = c4 & 63;
    int si = (b * 16 + h) * 2 + w;
    float s = g_scale[si];
    size_t base = ((size_t)(b * N_ + n)) * (3 * C_) + w * C_ + c4;
    float4 v = *(const float4*)&g_qkv[base];
    unsigned u0 = __nv_cvt_float_to_fp8(v.x * s, __NV_SATFINITE, __NV_E4M3);
    unsigned u1 = __nv_cvt_float_to_fp8(v.y * s, __NV_SATFINITE, __NV_E4M3);
    unsigned u2 = __nv_cvt_float_to_fp8(v.z * s, __NV_SATFINITE, __NV_E4M3);
    unsigned u3 = __nv_cvt_float_to_fp8(v.w * s, __NV_SATFINITE, __NV_E4M3);
    unsigned word = u0 | (u1 << 8) | (u2 << 16) | (u3 << 24);
    unsigned char* dst = (w == 0) ? g_q8 : g_k8;
    *(unsigned*)&dst[((size_t)((b * 16 + h) * N_ + n)) * 64 + d] = word;
}

// ---------------------------------------------------------------------------
// Tensor-core causal flash attention. QK^T fp8, PV fp16 (m16n8k16).
// Work-balanced: block processes q-tiles {p, 31-p}. Epilogue writes hi/lo halfs.
// ---------------------------------------------------------------------------
#define KSTR 17     // K8 tile row stride in words
#define VSTRH 72    // V tile row stride in halfs (36 words)
#define PSTRH 72    // P tile row stride in halfs (36 words)

__global__ void flash_fp8() {
    const int pid = blockIdx.x, h = blockIdx.y, b = blockIdx.z;
    __shared__ unsigned Ks8[64 * KSTR];
    __shared__ __half Vs[64 * VSTRH];
    __shared__ __half Ps[64 * PSTRH];

    const int tid = threadIdx.x;
    const int w = tid >> 5, lane = tid & 31;
    const int gid = lane >> 2, tig = lane & 3;
    const int bh = b * H_ + h;
    const unsigned* q8 = (const unsigned*)(g_q8 + (size_t)bh * N_ * D_);
    const unsigned* k8 = (const unsigned*)(g_k8 + (size_t)bh * N_ * D_);
    const float sc = g_iscale[bh * 2 + 0] * g_iscale[bh * 2 + 1] * 0.125f;

    const int prw0 = (w * 16 + gid) * (PSTRH / 2);       // word index
    const int prw1 = (w * 16 + gid + 8) * (PSTRH / 2);
    const int ph0 = (w * 16 + gid) * PSTRH;              // half index
    const int ph1 = (w * 16 + gid + 8) * PSTRH;

    for (int rep = 0; rep < 2; rep++) {
        const int qt = rep ? (N_ / 64 - 1 - pid) : pid;
        const int q0 = qt * 64;
        const int r0 = q0 + w * 16 + gid;

        unsigned qa[2][4];
#pragma unroll
        for (int ks = 0; ks < 2; ks++) {
            qa[ks][0] = q8[r0 * 16 + tig + 8 * ks];
            qa[ks][1] = q8[(r0 + 8) * 16 + tig + 8 * ks];
            qa[ks][2] = q8[r0 * 16 + tig + 4 + 8 * ks];
            qa[ks][3] = q8[(r0 + 8) * 16 + tig + 4 + 8 * ks];
        }

        float m0 = -INFINITY, m1 = -INFINITY, l0 = 0.f, l1 = 0.f;
        float o[8][4];
#pragma unroll
        for (int nt = 0; nt < 8; nt++)
#pragma unroll
            for (int e = 0; e < 4; e++) o[nt][e] = 0.f;

        for (int kt = 0; kt <= qt; kt++) {
            const int k0 = kt * 64;
            __syncthreads();
#pragma unroll
            for (int i = tid; i < 64 * 16; i += 128) {
                int rr = i >> 4, wd = i & 15;
                Ks8[rr * KSTR + wd] = k8[(k0 + rr) * 16 + wd];
            }
#pragma unroll
            for (int i = tid; i < 64 * 16; i += 128) {
                int rr = i >> 4, c4 = (i & 15) * 4;
                float4 v = *(const float4*)&g_qkv[((size_t)(b * N_ + k0 + rr)) * (3 * C_) + 2 * C_ + h * D_ + c4];
                HH hh;
                hh.a = __floats2half2_rn(v.x, v.y);
                hh.b = __floats2half2_rn(v.z, v.w);
                *(HH*)&Vs[rr * VSTRH + c4] = hh;
            }
            __syncthreads();

            float s[8][4];
#pragma unroll
            for (int nt = 0; nt < 8; nt++) {
                s[nt][0] = s[nt][1] = s[nt][2] = s[nt][3] = 0.f;
                const int col = nt * 8 + gid;
                unsigned b0 = Ks8[col * KSTR + tig];
                unsigned b1 = Ks8[col * KSTR + tig + 4];
                mma_e4m3(s[nt], qa[0], b0, b1);
                unsigned b2 = Ks8[col * KSTR + tig + 8];
                unsigned b3 = Ks8[col * KSTR + tig + 12];
                mma_e4m3(s[nt], qa[1], b2, b3);
            }
            const bool diag = (kt == qt);
#pragma unroll
            for (int nt = 0; nt < 8; nt++) {
                s[nt][0] *= sc; s[nt][1] *= sc; s[nt][2] *= sc; s[nt][3] *= sc;
                if (diag) {
                    int cl = nt * 8 + 2 * tig;
                    int rl0 = w * 16 + gid, rl1 = rl0 + 8;
                    if (cl > rl0)     s[nt][0] = -1e30f;
                    if (cl + 1 > rl0) s[nt][1] = -1e30f;
                    if (cl > rl1)     s[nt][2] = -1e30f;
                    if (cl + 1 > rl1) s[nt][3] = -1e30f;
                }
            }
            float mx0 = s[0][0], mx1 = s[0][2];
#pragma unroll
            for (int nt = 0; nt < 8; nt++) {
                mx0 = fmaxf(mx0, fmaxf(s[nt][0], s[nt][1]));
                mx1 = fmaxf(mx1, fmaxf(s[nt][2], s[nt][3]));
            }
            mx0 = fmaxf(mx0, __shfl_xor_sync(0xffffffffu, mx0, 1));
            mx0 = fmaxf(mx0, __shfl_xor_sync(0xffffffffu, mx0, 2));
            mx1 = fmaxf(mx1, __shfl_xor_sync(0xffffffffu, mx1, 1));
            mx1 = fmaxf(mx1, __shfl_xor_sync(0xffffffffu, mx1, 2));
            const float mn0 = fmaxf(m0, mx0), mn1 = fmaxf(m1, mx1);
            const float f0 = __expf(m0 - mn0), f1 = __expf(m1 - mn1);
            float sum0 = 0.f, sum1 = 0.f;
#pragma unroll
            for (int nt = 0; nt < 8; nt++) {
                float p0 = __expf(s[nt][0] - mn0);
                float p1 = __expf(s[nt][1] - mn0);
                float p2 = __expf(s[nt][2] - mn1);
                float p3 = __expf(s[nt][3] - mn1);
                sum0 += p0 + p1; sum1 += p2 + p3;
                *(__half2*)&Ps[ph0 + nt * 8 + 2 * tig] = __floats2half2_rn(p0, p1);
                *(__half2*)&Ps[ph1 + nt * 8 + 2 * tig] = __floats2half2_rn(p2, p3);
#pragma unroll
                for (int e = 0; e < 2; e++) { o[nt][e] *= f0; o[nt][e + 2] *= f1; }
            }
            sum0 += __shfl_xor_sync(0xffffffffu, sum0, 1);
            sum0 += __shfl_xor_sync(0xffffffffu, sum0, 2);
            sum1 += __shfl_xor_sync(0xffffffffu, sum1, 1);
            sum1 += __shfl_xor_sync(0xffffffffu, sum1, 2);
            l0 = l0 * f0 + sum0;
            l1 = l1 * f1 + sum1;
            m0 = mn0; m1 = mn1;
            __syncwarp();

            // O += P V (fp16 mma, V fragments via ldmatrix.trans)
            const unsigned* Pw = (const unsigned*)Ps;
#pragma unroll
            for (int kc = 0; kc < 4; kc++) {
                unsigned a[4];
                a[0] = Pw[prw0 + kc * 8 + tig];
                a[1] = Pw[prw1 + kc * 8 + tig];
                a[2] = Pw[prw0 + kc * 8 + tig + 4];
                a[3] = Pw[prw1 + kc * 8 + tig + 4];
#pragma unroll
                for (int nt = 0; nt < 8; nt++) {
                    unsigned b0, b1;
                    ldsm_x2t(b0, b1, &Vs[(kc * 16 + (lane & 15)) * VSTRH + nt * 8]);
                    mma_f16(o[nt], a, b0, b1);
                }
            }
        }

        // epilogue: write O as fp16 hi/lo split (consumed by proj GEMM)
        const float il0 = 1.f / l0, il1 = 1.f / l1;
#pragma unroll
        for (int nt = 0; nt < 8; nt++) {
            size_t c = h * D_ + nt * 8 + 2 * tig;
            size_t i0 = ((size_t)(b * N_ + r0)) * C_ + c;
            size_t i1 = ((size_t)(b * N_ + r0 + 8)) * C_ + c;
            float v0 = o[nt][0] * il0, v1 = o[nt][1] * il0;
            float v2 = o[nt][2] * il1, v3 = o[nt][3] * il1;
            __half h0 = __float2half_rn(v0), h1 = __float2half_rn(v1);
            __half h2 = __float2half_rn(v2), h3 = __float2half_rn(v3);
            *(__half2*)&g_atth[i0] = __halves2half2(h0, h1);
            *(__half2*)&g_atth[i1] = __halves2half2(h2, h3);
            *(__half2*)&g_attl[i0] = __halves2half2(
                __float2half_rn(v0 - __half2float(h0)), __float2half_rn(v1 - __half2float(h1)));
            *(__half2*)&g_attl[i1] = __halves2half2(
                __float2half_rn(v2 - __half2float(h2)), __float2half_rn(v3 - __half2float(h3)));
        }
    }
}

// ---------------------------------------------------------------------------
extern "C" void kernel_launch(void* const* d_in, const int* in_sizes, int n_in,
                              void* d_out, int out_size) {
    const float* x      = (const float*)d_in[0];   // [2,2048,1024]
    const float* w_qkv  = (const float*)d_in[1];   // [1024,3072]
    const float* w_proj = (const float*)d_in[2];   // [1024,1024]
    const float* b_proj = (const float*)d_in[3];   // [1024]
    float* out = (float*)d_out;                    // [2,2048,1024]

    float* qkv_ptr; cudaGetSymbolAddress((void**)&qkv_ptr, g_qkv);
    __half *xh, *xl, *wqh, *wql, *wph, *wpl, *ath, *atl;
    cudaGetSymbolAddress((void**)&xh,  g_xh);
    cudaGetSymbolAddress((void**)&xl,  g_xl);
    cudaGetSymbolAddress((void**)&wqh, g_wqh);
    cudaGetSymbolAddress((void**)&wql, g_wql);
    cudaGetSymbolAddress((void**)&wph, g_wph);
    cudaGetSymbolAddress((void**)&wpl, g_wpl);
    cudaGetSymbolAddress((void**)&ath, g_atth);
    cudaGetSymbolAddress((void**)&atl, g_attl);

    // 0) hi/lo fp16 splits of x, w_qkv, w_proj
    prep_split<<<(B_ * N_ * C_ / 4 + 255) / 256, 256>>>(x, xh, xl, B_ * N_ * C_ / 4);
    prep_split<<<(C_ * 3 * C_ / 4 + 255) / 256, 256>>>(w_qkv, wqh, wql, C_ * 3 * C_ / 4);
    prep_split<<<(C_ * C_ / 4 + 255) / 256, 256>>>(w_proj, wph, wpl, C_ * C_ / 4);

    // 1) QKV GEMM (fp16x3)
    {
        dim3 grid(3 * C_ / 128, (B_ * N_) / 128);
        gemm_f16x3<false><<<grid, 256>>>(xh, xl, wqh, wql, nullptr, qkv_ptr, B_ * N_, 3 * C_, C_);
    }
    // 2) amax -> scales
    {
        dim3 grid(8, 64);
        amax_part<<<grid, 256>>>();
        amax_fin<<<1, 64>>>();
    }
    // 3) fp8 quantize q,k
    quant_kernel<<<(B_ * N_ * 2 * (C_ / 4) + 255) / 256, 256>>>();
    // 4) tensor-core causal flash attention
    {
        dim3 grid(N_ / 128, H_, B_);
        flash_fp8<<<grid, 128>>>();
    }
    // 5) output projection + bias (fp16x3)
    {
        dim3 grid(C_ / 128, (B_ * N_) / 128);
        gemm_f16x3<true><<<grid, 256>>>(ath, atl, wph, wpl, b_proj, out, B_ * N_, C_, C_);
    }
}